// round 1
// baseline (speedup 1.0000x reference)
#include <cuda_runtime.h>
#include <math_constants.h>

#define NBATCH    512     // N*T
#define NTOKS     512
#define DIN       128
#define TOPK_N    12
#define NTHREADS  256
#define NWARPS    8
#define ROWS_PER_WARP (NTOKS / NWARPS)   // 64
#define CHUNK     128
#define XSTRIDE   132     // 528B row stride -> conflict-free LDS.128 (528 mod 128 = 16)

// ---------- small PTX helpers ----------
__device__ __forceinline__ float ex2f_fast(float x) {
    float r; asm("ex2.approx.f32 %0, %1;" : "=f"(r) : "f"(x)); return r;
}
__device__ __forceinline__ float rcpf_fast(float x) {
    float r; asm("rcp.approx.f32 %0, %1;" : "=f"(r) : "f"(x)); return r;
}
__device__ __forceinline__ unsigned long long pk2(float lo, float hi) {
    unsigned long long r; asm("mov.b64 %0, {%1, %2};" : "=l"(r) : "f"(lo), "f"(hi)); return r;
}
__device__ __forceinline__ void upk2(float& lo, float& hi, unsigned long long v) {
    asm("mov.b64 {%0, %1}, %2;" : "=f"(lo), "=f"(hi) : "l"(v));
}
__device__ __forceinline__ unsigned long long fma2(unsigned long long a,
                                                   unsigned long long b,
                                                   unsigned long long c) {
    unsigned long long r;
    asm("fma.rn.f32x2 %0, %1, %2, %3;" : "=l"(r) : "l"(a), "l"(b), "l"(c));
    return r;
}

// smem layout (floats):
//   xs   [CHUNK][XSTRIDE]        16896
//   wks  [128][4]                  512
//   wqs  [128][4]                  512
//   ks   [512][4] (pre-scaled)    2048
//   qs   [512][4]                 2048
//   A    [512]                     512
//   sel  [12] ints                  12
#define SM_FLOATS (CHUNK*XSTRIDE + 512 + 512 + 2048 + 2048 + 512 + 16)

extern __shared__ float smem[];

__global__ __launch_bounds__(NTHREADS, 2)
void sparse_attn_kernel(const float* __restrict__ x,
                        const float* __restrict__ wk,
                        const float* __restrict__ wq,
                        float* __restrict__ out)
{
    float* xs  = smem;                       // [CHUNK][XSTRIDE]
    float* wks = xs + CHUNK * XSTRIDE;       // [128][4]
    float* wqs = wks + 512;
    float* ks  = wqs + 512;                  // [512][4], scaled by (1/sqrt(D))*log2(e)
    float* qs  = ks + 2048;                  // [512][4]
    float* Ash = qs + 2048;                  // [512]
    int*   sel = (int*)(Ash + NTOKS);        // [12]

    const int tid  = threadIdx.x;
    const int lane = tid & 31;
    const int warp = tid >> 5;
    const int b    = blockIdx.x;

    const float* xb = x + (size_t)b * NTOKS * DIN;

    // ---- init: weights to smem, zero A ----
    for (int i = tid; i < 512; i += NTHREADS) { wks[i] = wk[i]; wqs[i] = wq[i]; }
    for (int i = tid; i < NTOKS; i += NTHREADS) Ash[i] = 0.f;
    __syncthreads();

    // fold softmax scale and log2(e) into k so logits are in log2 units
    const float KSCALE = 0.0883883476483184405f * 1.4426950408889634074f;

    // ================= Stage 1: k,q projection =================
    const int t_local = tid & (CHUNK - 1);
    const int half    = tid >> 7;  // 0 -> k outputs, 1 -> q outputs
    const float4* wsel4 = (const float4*)(half ? wqs : wks);

    for (int c = 0; c < NTOKS / CHUNK; ++c) {
        // coalesced gmem -> smem (float4), conflict-free STS
        const float4* xg4 = (const float4*)(xb + (size_t)c * CHUNK * DIN);
        #pragma unroll
        for (int it = 0; it < (CHUNK * 32) / NTHREADS; ++it) {   // 16 iters
            int idx = tid + it * NTHREADS;                        // = t*32 + e4
            int t  = idx >> 5;
            int e4 = idx & 31;
            float4 v = xg4[idx];
            *(float4*)(xs + t * XSTRIDE + e4 * 4) = v;
        }
        __syncthreads();

        // each thread: one (token, half) -> 4 projection outputs
        float a0 = 0.f, a1 = 0.f, a2 = 0.f, a3 = 0.f;
        const float4* xr = (const float4*)(xs + t_local * XSTRIDE);
        #pragma unroll
        for (int e4 = 0; e4 < 32; ++e4) {
            float4 xv = xr[e4];                 // conflict-free (stride 528B)
            float4 w0 = wsel4[e4 * 4 + 0];      // broadcast
            float4 w1 = wsel4[e4 * 4 + 1];
            float4 w2 = wsel4[e4 * 4 + 2];
            float4 w3 = wsel4[e4 * 4 + 3];
            a0 = fmaf(xv.x, w0.x, a0); a1 = fmaf(xv.x, w0.y, a1);
            a2 = fmaf(xv.x, w0.z, a2); a3 = fmaf(xv.x, w0.w, a3);
            a0 = fmaf(xv.y, w1.x, a0); a1 = fmaf(xv.y, w1.y, a1);
            a2 = fmaf(xv.y, w1.z, a2); a3 = fmaf(xv.y, w1.w, a3);
            a0 = fmaf(xv.z, w2.x, a0); a1 = fmaf(xv.z, w2.y, a1);
            a2 = fmaf(xv.z, w2.z, a2); a3 = fmaf(xv.z, w2.w, a3);
            a0 = fmaf(xv.w, w3.x, a0); a1 = fmaf(xv.w, w3.y, a1);
            a2 = fmaf(xv.w, w3.z, a2); a3 = fmaf(xv.w, w3.w, a3);
        }
        int token = c * CHUNK + t_local;
        if (half == 0)
            ((float4*)ks)[token] = make_float4(a0 * KSCALE, a1 * KSCALE,
                                               a2 * KSCALE, a3 * KSCALE);
        else
            ((float4*)qs)[token] = make_float4(a0, a1, a2, a3);
        __syncthreads();  // xs reuse + ks/qs visibility
    }

    // ================= Stage 2: softmax-sum A =================
    // Lane owns columns m = lane + 32*j, j = 0..15; pairs (2i, 2i+1) packed f32x2.
    unsigned long long Q[8][4];
    #pragma unroll
    for (int i = 0; i < 8; ++i) {
        int mA = lane + 64 * i;
        float4 qa = ((const float4*)qs)[mA];
        float4 qb = ((const float4*)qs)[mA + 32];
        Q[i][0] = pk2(qa.x, qb.x);
        Q[i][1] = pk2(qa.y, qb.y);
        Q[i][2] = pk2(qa.z, qb.z);
        Q[i][3] = pk2(qa.w, qb.w);
    }

    float Aacc[16];
    #pragma unroll
    for (int j = 0; j < 16; ++j) Aacc[j] = 0.f;

    #pragma unroll 1
    for (int r = 0; r < ROWS_PER_WARP; ++r) {
        int n = warp * ROWS_PER_WARP + r;
        float4 kn = ((const float4*)ks)[n];         // broadcast LDS.128
        unsigned long long k0 = pk2(kn.x, kn.x);
        unsigned long long k1 = pk2(kn.y, kn.y);
        unsigned long long k2 = pk2(kn.z, kn.z);
        unsigned long long k3 = pk2(kn.w, kn.w);

        float l[16];
        #pragma unroll
        for (int i = 0; i < 8; ++i) {
            unsigned long long acc = 0ull;          // (0.f, 0.f)
            acc = fma2(Q[i][0], k0, acc);
            acc = fma2(Q[i][1], k1, acc);
            acc = fma2(Q[i][2], k2, acc);
            acc = fma2(Q[i][3], k3, acc);
            upk2(l[2 * i], l[2 * i + 1], acc);
        }

        // row max (lane-local tree + warp butterfly)
        float mx = l[0];
        #pragma unroll
        for (int j = 1; j < 16; ++j) mx = fmaxf(mx, l[j]);
        #pragma unroll
        for (int off = 16; off > 0; off >>= 1)
            mx = fmaxf(mx, __shfl_xor_sync(0xffffffffu, mx, off));

        // exp2 + denom
        float s = 0.f;
        #pragma unroll
        for (int j = 0; j < 16; ++j) {
            float p = ex2f_fast(l[j] - mx);
            l[j] = p;
            s += p;
        }
        #pragma unroll
        for (int off = 16; off > 0; off >>= 1)
            s += __shfl_xor_sync(0xffffffffu, s, off);

        float inv = rcpf_fast(s);
        #pragma unroll
        for (int j = 0; j < 16; ++j)
            Aacc[j] = fmaf(l[j], inv, Aacc[j]);
    }

    #pragma unroll
    for (int j = 0; j < 16; ++j)
        atomicAdd(&Ash[lane + 32 * j], Aacc[j]);
    __syncthreads();

    // ================= Stage 3: top-12 (JAX order: desc, ties -> lower idx) ====
    if (warp == 0) {
        #pragma unroll 1
        for (int t = 0; t < TOPK_N; ++t) {
            float bv = -CUDART_INF_F;
            int   bi = NTOKS;
            #pragma unroll
            for (int j = 0; j < 16; ++j) {
                int m = lane + 32 * j;          // ascending m within lane
                float v = Ash[m];
                if (v > bv) { bv = v; bi = m; } // strict > keeps lowest index
            }
            #pragma unroll
            for (int off = 16; off > 0; off >>= 1) {
                float ov = __shfl_xor_sync(0xffffffffu, bv, off);
                int   oi = __shfl_xor_sync(0xffffffffu, bi, off);
                if (ov > bv || (ov == bv && oi < bi)) { bv = ov; bi = oi; }
            }
            if (lane == 0) { sel[t] = bi; Ash[bi] = -CUDART_INF_F; }
            __syncwarp();
        }
    }
    __syncthreads();

    // ================= Stage 4: gather =================
    const float4* xb4 = (const float4*)xb;
    float4* ob4 = (float4*)(out + (size_t)b * TOPK_N * DIN);
    for (int i = tid; i < TOPK_N * 32; i += NTHREADS) {
        int t  = i >> 5;
        int e4 = i & 31;
        ob4[i] = xb4[sel[t] * 32 + e4];
    }
}

extern "C" void kernel_launch(void* const* d_in, const int* in_sizes, int n_in,
                              void* d_out, int out_size)
{
    const float* x  = (const float*)d_in[0];
    const float* wk = (const float*)d_in[1];
    const float* wq = (const float*)d_in[2];
    float* out = (float*)d_out;
    (void)in_sizes; (void)n_in; (void)out_size;

    int smem_bytes = SM_FLOATS * (int)sizeof(float);
    cudaFuncSetAttribute(sparse_attn_kernel,
                         cudaFuncAttributeMaxDynamicSharedMemorySize, smem_bytes);
    sparse_attn_kernel<<<NBATCH, NTHREADS, smem_bytes>>>(x, wk, wq, out);
}

// round 2
// speedup vs baseline: 1.1404x; 1.1404x over previous
#include <cuda_runtime.h>
#include <math_constants.h>
#include <cstdint>

#define NBATCH    512
#define NTOKS     512
#define DIN       128
#define TOPK_N    12
#define NTHREADS  256
#define NWARPS    8
#define CHUNK     64
#define NCHUNK    (NTOKS / CHUNK)       // 8
#define XSTRIDE   132                   // 528B token stride: conflict-free LDS.128
#define XBUF      (CHUNK * XSTRIDE)     // 8448 floats per buffer

// ---------- PTX helpers ----------
__device__ __forceinline__ float ex2f_fast(float x) {
    float r; asm("ex2.approx.f32 %0, %1;" : "=f"(r) : "f"(x)); return r;
}
__device__ __forceinline__ float rcpf_fast(float x) {
    float r; asm("rcp.approx.f32 %0, %1;" : "=f"(r) : "f"(x)); return r;
}
__device__ __forceinline__ unsigned long long pk2(float lo, float hi) {
    unsigned long long r; asm("mov.b64 %0, {%1, %2};" : "=l"(r) : "f"(lo), "f"(hi)); return r;
}
__device__ __forceinline__ void upk2(float& lo, float& hi, unsigned long long v) {
    asm("mov.b64 {%0, %1}, %2;" : "=f"(lo), "=f"(hi) : "l"(v));
}
__device__ __forceinline__ unsigned long long fma2(unsigned long long a,
                                                   unsigned long long b,
                                                   unsigned long long c) {
    unsigned long long r;
    asm("fma.rn.f32x2 %0, %1, %2, %3;" : "=l"(r) : "l"(a), "l"(b), "l"(c));
    return r;
}
__device__ __forceinline__ unsigned long long add2(unsigned long long a,
                                                   unsigned long long b) {
    unsigned long long r;
    asm("add.rn.f32x2 %0, %1, %2;" : "=l"(r) : "l"(a), "l"(b));
    return r;
}
__device__ __forceinline__ void cp_async16(uint32_t saddr, const void* gaddr) {
    asm volatile("cp.async.cg.shared.global [%0], [%1], 16;" :: "r"(saddr), "l"(gaddr));
}
#define CP_COMMIT() asm volatile("cp.async.commit_group;")

// order-preserving float<->uint key (works for all finite floats incl. -inf)
__device__ __forceinline__ unsigned fkey(float v) {
    int b = __float_as_int(v);
    return (unsigned)b ^ (unsigned)((b >> 31) | 0x80000000);
}
__device__ __forceinline__ float funkey(unsigned k) {
    int b = (k & 0x80000000u) ? (int)(k ^ 0x80000000u) : ~(int)k;
    return __int_as_float(b);
}
__device__ __forceinline__ float redux_maxf(float v) {
    unsigned w = __reduce_max_sync(0xffffffffu, fkey(v));
    return funkey(w);
}

// smem layout (floats)
#define OFF_XS    0
#define OFF_WKS   (OFF_XS + 2 * XBUF)       // 16896
#define OFF_WQS   (OFF_WKS + 512)
#define OFF_KS    (OFF_WQS + 512)           // [512][4]
#define OFF_QS    (OFF_KS + 2048)           // [512][4]
#define OFF_A     (OFF_QS + 2048)           // [512]
#define OFF_SEL   (OFF_A + 512)             // 16 ints
#define OFF_SC    (OFF_SEL + 16)            // 128 float4 scratch
#define SM_FLOATS (OFF_SC + 512)            // 23056 floats = 92224 B

extern __shared__ float smem[];

__global__ __launch_bounds__(NTHREADS, 2)
void sparse_attn_kernel(const float* __restrict__ x,
                        const float* __restrict__ wk,
                        const float* __restrict__ wq,
                        float* __restrict__ out)
{
    float* xs  = smem + OFF_XS;
    float* wks = smem + OFF_WKS;
    float* wqs = smem + OFF_WQS;
    float* ks  = smem + OFF_KS;
    float* qs  = smem + OFF_QS;
    float* Ash = smem + OFF_A;
    int*   sel = (int*)(smem + OFF_SEL);
    float4* sc4 = (float4*)(smem + OFF_SC);

    const int tid  = threadIdx.x;
    const int lane = tid & 31;
    const int warp = tid >> 5;
    const int b    = blockIdx.x;

    const float* xb = x + (size_t)b * NTOKS * DIN;
    const float4* xg4 = (const float4*)xb;

    for (int i = tid; i < 512; i += NTHREADS) { wks[i] = wk[i]; wqs[i] = wq[i]; }
    for (int i = tid; i < NTOKS; i += NTHREADS) Ash[i] = 0.f;

    // (1/sqrt(128)) * log2(e): logits in log2 units
    const float KSCALE = 0.0883883476483184405f * 1.4426950408889634074f;

    // ================= Stage 1: projection, cp.async double-buffered ========
    const int token = tid & 63;
    const int dhalf = (tid >> 6) & 1;
    const int proj  = (tid >> 7) & 1;
    const float4* wsel4 = (const float4*)(proj ? wqs : wks);
    float4* ks4w = (float4*)ks;
    float4* qs4w = (float4*)qs;

    uint32_t xs_s = (uint32_t)__cvta_generic_to_shared(xs);

    // prologue: chunk 0
    {
        #pragma unroll
        for (int k2 = 0; k2 < 8; ++k2) {
            int idx = tid + k2 * NTHREADS;            // 0..2047
            int t = idx >> 5, e4 = idx & 31;
            cp_async16(xs_s + (uint32_t)(t * XSTRIDE + e4 * 4) * 4u, xg4 + idx);
        }
        CP_COMMIT();
    }
    __syncthreads();   // covers wks/wqs/Ash init too

    for (int c = 0; c < NCHUNK; ++c) {
        if (c < NCHUNK - 1) {
            int buf = (c + 1) & 1;
            #pragma unroll
            for (int k2 = 0; k2 < 8; ++k2) {
                int idx = tid + k2 * NTHREADS;
                int t = idx >> 5, e4 = idx & 31;
                cp_async16(xs_s + (uint32_t)(buf * XBUF + t * XSTRIDE + e4 * 4) * 4u,
                           xg4 + (c + 1) * (CHUNK * DIN / 4) + idx);
            }
            CP_COMMIT();
            asm volatile("cp.async.wait_group 1;");
        } else {
            asm volatile("cp.async.wait_group 0;");
        }
        __syncthreads();

        const float4* xr = (const float4*)(xs + (c & 1) * XBUF + token * XSTRIDE + dhalf * 64);
        float a0 = 0.f, a1 = 0.f, a2 = 0.f, a3 = 0.f;
        #pragma unroll
        for (int i = 0; i < 16; ++i) {
            float4 xv = xr[i];
            int e4 = dhalf * 16 + i;
            float4 w0 = wsel4[e4 * 4 + 0];
            float4 w1 = wsel4[e4 * 4 + 1];
            float4 w2 = wsel4[e4 * 4 + 2];
            float4 w3 = wsel4[e4 * 4 + 3];
            a0 = fmaf(xv.x, w0.x, a0); a1 = fmaf(xv.x, w0.y, a1);
            a2 = fmaf(xv.x, w0.z, a2); a3 = fmaf(xv.x, w0.w, a3);
            a0 = fmaf(xv.y, w1.x, a0); a1 = fmaf(xv.y, w1.y, a1);
            a2 = fmaf(xv.y, w1.z, a2); a3 = fmaf(xv.y, w1.w, a3);
            a0 = fmaf(xv.z, w2.x, a0); a1 = fmaf(xv.z, w2.y, a1);
            a2 = fmaf(xv.z, w2.z, a2); a3 = fmaf(xv.z, w2.w, a3);
            a0 = fmaf(xv.w, w3.x, a0); a1 = fmaf(xv.w, w3.y, a1);
            a2 = fmaf(xv.w, w3.z, a2); a3 = fmaf(xv.w, w3.w, a3);
        }
        if (dhalf) sc4[proj * 64 + token] = make_float4(a0, a1, a2, a3);
        __syncthreads();
        if (!dhalf) {
            float4 p = sc4[proj * 64 + token];
            a0 += p.x; a1 += p.y; a2 += p.z; a3 += p.w;
            int tk = c * CHUNK + token;
            if (proj == 0)
                ks4w[tk] = make_float4(a0 * KSCALE, a1 * KSCALE, a2 * KSCALE, a3 * KSCALE);
            else
                qs4w[tk] = make_float4(a0, a1, a2, a3);
        }
        __syncthreads();
    }

    // ===== pack q into f32x2 pairs, overlaying xs (dead after stage 1) ======
    // entry (i,lane), i=0..7: pairs for columns (lane+64i, lane+64i+32)
    unsigned long long* qp = (unsigned long long*)xs;
    {
        int i = tid >> 5, ln = tid & 31;
        const float4* qs4 = (const float4*)qs;
        float4 qa = qs4[ln + 64 * i];
        float4 qb = qs4[ln + 64 * i + 32];
        unsigned long long* dst = qp + (size_t)(i * 32 + ln) * 4;
        dst[0] = pk2(qa.x, qb.x);
        dst[1] = pk2(qa.y, qb.y);
        dst[2] = pk2(qa.z, qb.z);
        dst[3] = pk2(qa.w, qb.w);
    }
    __syncthreads();

    // ================= Stage 2: softmax-sum A, 2 rows per iteration =========
    const float4* ks4 = (const float4*)ks;
    const ulonglong2* qv = (const ulonglong2*)qp;

    unsigned long long A2[8];
    #pragma unroll
    for (int i = 0; i < 8; ++i) A2[i] = 0ull;

    #pragma unroll 1
    for (int rp = 0; rp < 32; ++rp) {
        int n = warp * 64 + rp * 2;
        float4 ka = ks4[n];
        float4 kb = ks4[n + 1];
        unsigned long long ka0 = pk2(ka.x, ka.x), ka1 = pk2(ka.y, ka.y);
        unsigned long long ka2 = pk2(ka.z, ka.z), ka3 = pk2(ka.w, ka.w);
        unsigned long long kb0 = pk2(kb.x, kb.x), kb1 = pk2(kb.y, kb.y);
        unsigned long long kb2 = pk2(kb.z, kb.z), kb3 = pk2(kb.w, kb.w);

        unsigned long long e0[8], e1[8];
        #pragma unroll
        for (int i = 0; i < 8; ++i) {
            ulonglong2 qA = qv[(i * 32 + lane) * 2];
            ulonglong2 qB = qv[(i * 32 + lane) * 2 + 1];
            unsigned long long a = fma2(qA.x, ka0, 0ull);
            unsigned long long bb = fma2(qA.x, kb0, 0ull);
            a  = fma2(qA.y, ka1, a);  bb = fma2(qA.y, kb1, bb);
            a  = fma2(qB.x, ka2, a);  bb = fma2(qB.x, kb2, bb);
            a  = fma2(qB.y, ka3, a);  bb = fma2(qB.y, kb3, bb);
            e0[i] = a; e1[i] = bb;
        }

        // exact row max via lane-local tree + one REDUX each
        float mx0 = -CUDART_INF_F, mx1 = -CUDART_INF_F;
        #pragma unroll
        for (int i = 0; i < 8; ++i) {
            float lo, hi;
            upk2(lo, hi, e0[i]); mx0 = fmaxf(mx0, fmaxf(lo, hi));
            upk2(lo, hi, e1[i]); mx1 = fmaxf(mx1, fmaxf(lo, hi));
        }
        mx0 = redux_maxf(mx0);
        mx1 = redux_maxf(mx1);

        // exp2(l - M), keep numerators packed
        unsigned long long M0 = pk2(-mx0, -mx0), M1 = pk2(-mx1, -mx1);
        #pragma unroll
        for (int i = 0; i < 8; ++i) {
            float lo, hi;
            unsigned long long d0 = add2(e0[i], M0);
            upk2(lo, hi, d0);
            e0[i] = pk2(ex2f_fast(lo), ex2f_fast(hi));
            unsigned long long d1 = add2(e1[i], M1);
            upk2(lo, hi, d1);
            e1[i] = pk2(ex2f_fast(lo), ex2f_fast(hi));
        }

        // lane sum via packed tree, then 5-shfl warp sum (2 chains interleaved)
        float s0, s1;
        {
            unsigned long long t0 = add2(add2(add2(e0[0], e0[1]), add2(e0[2], e0[3])),
                                         add2(add2(e0[4], e0[5]), add2(e0[6], e0[7])));
            unsigned long long t1 = add2(add2(add2(e1[0], e1[1]), add2(e1[2], e1[3])),
                                         add2(add2(e1[4], e1[5]), add2(e1[6], e1[7])));
            float lo, hi;
            upk2(lo, hi, t0); s0 = lo + hi;
            upk2(lo, hi, t1); s1 = lo + hi;
        }
        #pragma unroll
        for (int off = 16; off > 0; off >>= 1) {
            s0 += __shfl_xor_sync(0xffffffffu, s0, off);
            s1 += __shfl_xor_sync(0xffffffffu, s1, off);
        }
        unsigned long long v0, v1;
        {
            float i0 = rcpf_fast(s0), i1 = rcpf_fast(s1);
            v0 = pk2(i0, i0); v1 = pk2(i1, i1);
        }
        #pragma unroll
        for (int i = 0; i < 8; ++i) {
            A2[i] = fma2(e0[i], v0, A2[i]);
            A2[i] = fma2(e1[i], v1, A2[i]);
        }
    }

    #pragma unroll
    for (int i = 0; i < 8; ++i) {
        float lo, hi;
        upk2(lo, hi, A2[i]);
        atomicAdd(&Ash[lane + 64 * i], lo);
        atomicAdd(&Ash[lane + 64 * i + 32], hi);
    }
    __syncthreads();

    // ============ Stage 3: top-12, register-resident + REDUX argmax =========
    if (warp == 0) {
        float av[16];
        #pragma unroll
        for (int j = 0; j < 16; ++j) av[j] = Ash[lane + 32 * j];

        #pragma unroll 1
        for (int t = 0; t < TOPK_N; ++t) {
            float bv = -CUDART_INF_F;
            int   bi = 0x7fffffff;
            #pragma unroll
            for (int j = 0; j < 16; ++j) {
                float v = av[j];
                int idx = lane + 32 * j;
                if (v > bv) { bv = v; bi = idx; }   // ascending idx, strict >
            }
            unsigned key = fkey(bv);
            unsigned win = __reduce_max_sync(0xffffffffu, key);
            unsigned cand = (key == win) ? (unsigned)bi : 0x7fffffffu;
            int idx = (int)__reduce_min_sync(0xffffffffu, cand);
            if (lane == 0) sel[t] = idx;
            #pragma unroll
            for (int j = 0; j < 16; ++j)
                if (idx == lane + 32 * j) av[j] = -CUDART_INF_F;
        }
    }
    __syncthreads();

    // ================= Stage 4: gather =================
    float4* ob4 = (float4*)(out + (size_t)b * TOPK_N * DIN);
    for (int i = tid; i < TOPK_N * 32; i += NTHREADS) {
        int t  = i >> 5;
        int e4 = i & 31;
        ob4[i] = xg4[sel[t] * 32 + e4];
    }
}

extern "C" void kernel_launch(void* const* d_in, const int* in_sizes, int n_in,
                              void* d_out, int out_size)
{
    const float* x  = (const float*)d_in[0];
    const float* wk = (const float*)d_in[1];
    const float* wq = (const float*)d_in[2];
    float* out = (float*)d_out;
    (void)in_sizes; (void)n_in; (void)out_size;

    int smem_bytes = SM_FLOATS * (int)sizeof(float);
    cudaFuncSetAttribute(sparse_attn_kernel,
                         cudaFuncAttributeMaxDynamicSharedMemorySize, smem_bytes);
    sparse_attn_kernel<<<NBATCH, NTHREADS, smem_bytes>>>(x, wk, wq, out);
}

// round 4
// speedup vs baseline: 1.1594x; 1.0167x over previous
#include <cuda_runtime.h>
#include <math_constants.h>
#include <cstdint>

#define NBATCH    512
#define NTOKS     512
#define DIN       128
#define TOPK_N    12
#define NTHREADS  256

// global scratch (contiguous per tensor for coalesced K2 loads)
__device__ float4 g_k[NBATCH * NTOKS];   // pre-scaled k
__device__ float4 g_q[NBATCH * NTOKS];

// ---------- PTX helpers ----------
__device__ __forceinline__ float ex2f_fast(float x) {
    float r; asm("ex2.approx.f32 %0, %1;" : "=f"(r) : "f"(x)); return r;
}
__device__ __forceinline__ float rcpf_fast(float x) {
    float r; asm("rcp.approx.f32 %0, %1;" : "=f"(r) : "f"(x)); return r;
}
__device__ __forceinline__ unsigned long long pk2(float lo, float hi) {
    unsigned long long r; asm("mov.b64 %0, {%1, %2};" : "=l"(r) : "f"(lo), "f"(hi)); return r;
}
__device__ __forceinline__ void upk2(float& lo, float& hi, unsigned long long v) {
    asm("mov.b64 {%0, %1}, %2;" : "=f"(lo), "=f"(hi) : "l"(v));
}
__device__ __forceinline__ unsigned long long fma2(unsigned long long a,
                                                   unsigned long long b,
                                                   unsigned long long c) {
    unsigned long long r;
    asm("fma.rn.f32x2 %0, %1, %2, %3;" : "=l"(r) : "l"(a), "l"(b), "l"(c));
    return r;
}
__device__ __forceinline__ unsigned long long add2(unsigned long long a,
                                                   unsigned long long b) {
    unsigned long long r;
    asm("add.rn.f32x2 %0, %1, %2;" : "=l"(r) : "l"(a), "l"(b));
    return r;
}
__device__ __forceinline__ void cp_async16(uint32_t saddr, const void* gaddr) {
    asm volatile("cp.async.cg.shared.global [%0], [%1], 16;" :: "r"(saddr), "l"(gaddr));
}
__device__ __forceinline__ unsigned fkey(float v) {
    int b = __float_as_int(v);
    return (unsigned)b ^ (unsigned)((b >> 31) | 0x80000000);
}
__device__ __forceinline__ float funkey(unsigned k) {
    int b = (k & 0x80000000u) ? (int)(k ^ 0x80000000u) : ~(int)k;
    return __int_as_float(b);
}
__device__ __forceinline__ float redux_maxf(float v) {
    return funkey(__reduce_max_sync(0xffffffffu, fkey(v)));
}
// near-exact fp32 warp sum of nonneg partials (each <= 16) via split fixed point.
// quantization 2^-26 per partial -> rel err <= ~2.4e-7 on s (>= 1).
__device__ __forceinline__ float redux_sum_pos(float partial) {
    unsigned u = __float2uint_rn(partial * 67108864.0f);      // * 2^26, <= 2^30
    unsigned losum = __reduce_add_sync(0xffffffffu, u & 0xFFFFu);
    unsigned hisum = __reduce_add_sync(0xffffffffu, u >> 16);
    return fmaf((float)hisum, 65536.0f, (float)losum) * 1.490116119384765625e-8f; // 2^-26
}

// ======================= K1: projection =======================
// grid (8, 512) = (chunk of 64 tokens, batch); 256 threads
__global__ __launch_bounds__(NTHREADS)
void proj_kernel(const float* __restrict__ x,
                 const float* __restrict__ wk,
                 const float* __restrict__ wq)
{
    __shared__ float xs[64 * 132];        // 528B token stride, conflict-free
    __shared__ float wks[512], wqs[512];
    __shared__ float4 sc4[128];

    const int tid = threadIdx.x;
    const int c = blockIdx.x;
    const int b = blockIdx.y;
    const float4* xg4 = (const float4*)(x + ((size_t)b * NTOKS + (size_t)c * 64) * DIN);

    for (int i = tid; i < 512; i += NTHREADS) { wks[i] = wk[i]; wqs[i] = wq[i]; }

    uint32_t xs_s = (uint32_t)__cvta_generic_to_shared(xs);
    #pragma unroll
    for (int k2 = 0; k2 < 8; ++k2) {
        int idx = tid + k2 * NTHREADS;          // 0..2047
        int t = idx >> 5, e4 = idx & 31;
        cp_async16(xs_s + (uint32_t)(t * 132 + e4 * 4) * 4u, xg4 + idx);
    }
    asm volatile("cp.async.commit_group;");
    asm volatile("cp.async.wait_group 0;");
    __syncthreads();

    const int token = tid & 63;
    const int dhalf = (tid >> 6) & 1;
    const int proj  = tid >> 7;
    const float4* wsel4 = (const float4*)(proj ? wqs : wks);
    const float4* xr = (const float4*)(xs + token * 132 + dhalf * 64);

    float a0 = 0.f, a1 = 0.f, a2 = 0.f, a3 = 0.f;
    #pragma unroll
    for (int i = 0; i < 16; ++i) {
        float4 xv = xr[i];
        int e4 = dhalf * 16 + i;
        float4 w0 = wsel4[e4 * 4 + 0];
        float4 w1 = wsel4[e4 * 4 + 1];
        float4 w2 = wsel4[e4 * 4 + 2];
        float4 w3 = wsel4[e4 * 4 + 3];
        a0 = fmaf(xv.x, w0.x, a0); a1 = fmaf(xv.x, w0.y, a1);
        a2 = fmaf(xv.x, w0.z, a2); a3 = fmaf(xv.x, w0.w, a3);
        a0 = fmaf(xv.y, w1.x, a0); a1 = fmaf(xv.y, w1.y, a1);
        a2 = fmaf(xv.y, w1.z, a2); a3 = fmaf(xv.y, w1.w, a3);
        a0 = fmaf(xv.z, w2.x, a0); a1 = fmaf(xv.z, w2.y, a1);
        a2 = fmaf(xv.z, w2.z, a2); a3 = fmaf(xv.z, w2.w, a3);
        a0 = fmaf(xv.w, w3.x, a0); a1 = fmaf(xv.w, w3.y, a1);
        a2 = fmaf(xv.w, w3.z, a2); a3 = fmaf(xv.w, w3.w, a3);
    }
    if (dhalf) sc4[proj * 64 + token] = make_float4(a0, a1, a2, a3);
    __syncthreads();
    if (!dhalf) {
        float4 p = sc4[proj * 64 + token];
        a0 += p.x; a1 += p.y; a2 += p.z; a3 += p.w;
        // (1/sqrt(128)) * log2(e) folded into k
        const float KSCALE = 0.0883883476483184405f * 1.4426950408889634074f;
        size_t o = (size_t)b * NTOKS + (size_t)c * 64 + token;
        if (proj == 0)
            g_k[o] = make_float4(a0 * KSCALE, a1 * KSCALE, a2 * KSCALE, a3 * KSCALE);
        else
            g_q[o] = make_float4(a0, a1, a2, a3);
    }
}

// ======================= K2: scores + softmax-sum + topk + gather ===========
__global__ __launch_bounds__(NTHREADS, 2)
void attn_kernel(const float* __restrict__ x, float* __restrict__ out)
{
    __shared__ float4 ks4[NTOKS];                 // pre-scaled k
    __shared__ unsigned long long qp[256 * 4];    // packed q pairs
    __shared__ float Ash[NTOKS];
    __shared__ int sel[16];

    const int tid  = threadIdx.x;
    const int lane = tid & 31;
    const int warp = tid >> 5;
    const int b    = blockIdx.x;
    const float4* kg = g_k + (size_t)b * NTOKS;
    const float4* qg = g_q + (size_t)b * NTOKS;

    // load k (coalesced)
    #pragma unroll
    for (int it = 0; it < 2; ++it) {
        int t = tid + it * NTHREADS;
        ks4[t] = kg[t];
    }
    // load + pack q: entry (i*32+ln) holds pairs for cols (ln+64i, ln+64i+32)
    {
        int i = tid >> 5, ln = tid & 31;
        int m = ln + 64 * i;
        float4 qa = qg[m];
        float4 qb = qg[m + 32];
        unsigned long long* dst = qp + (size_t)(i * 32 + ln) * 4;
        dst[0] = pk2(qa.x, qb.x);
        dst[1] = pk2(qa.y, qb.y);
        dst[2] = pk2(qa.z, qb.z);
        dst[3] = pk2(qa.w, qb.w);
    }
    for (int i = tid; i < NTOKS; i += NTHREADS) Ash[i] = 0.f;
    __syncthreads();

    // Q registers: lane owns cols lane+32j; pairs (lane+64i, lane+64i+32)
    unsigned long long Q[8][4];
    #pragma unroll
    for (int i = 0; i < 8; ++i) {
        const unsigned long long* src = qp + (size_t)(i * 32 + lane) * 4;
        Q[i][0] = src[0]; Q[i][1] = src[1]; Q[i][2] = src[2]; Q[i][3] = src[3];
    }

    unsigned long long A2[8];
    #pragma unroll
    for (int i = 0; i < 8; ++i) A2[i] = 0ull;

    #pragma unroll 1
    for (int rp = 0; rp < 32; ++rp) {
        int n = warp * 64 + rp * 2;
        float4 ka = ks4[n];
        float4 kb = ks4[n + 1];
        unsigned long long ka0 = pk2(ka.x, ka.x), ka1 = pk2(ka.y, ka.y);
        unsigned long long ka2 = pk2(ka.z, ka.z), ka3 = pk2(ka.w, ka.w);
        unsigned long long kb0 = pk2(kb.x, kb.x), kb1 = pk2(kb.y, kb.y);
        unsigned long long kb2 = pk2(kb.z, kb.z), kb3 = pk2(kb.w, kb.w);

        unsigned long long e0[8], e1[8];
        #pragma unroll
        for (int i = 0; i < 8; ++i) {
            unsigned long long a  = fma2(Q[i][0], ka0, 0ull);
            unsigned long long bb = fma2(Q[i][0], kb0, 0ull);
            a  = fma2(Q[i][1], ka1, a);  bb = fma2(Q[i][1], kb1, bb);
            a  = fma2(Q[i][2], ka2, a);  bb = fma2(Q[i][2], kb2, bb);
            a  = fma2(Q[i][3], ka3, a);  bb = fma2(Q[i][3], kb3, bb);
            e0[i] = a; e1[i] = bb;
        }

        // exact per-row max: lane tree + one REDUX each
        float mx0 = -CUDART_INF_F, mx1 = -CUDART_INF_F;
        #pragma unroll
        for (int i = 0; i < 8; ++i) {
            float lo, hi;
            upk2(lo, hi, e0[i]); mx0 = fmaxf(mx0, fmaxf(lo, hi));
            upk2(lo, hi, e1[i]); mx1 = fmaxf(mx1, fmaxf(lo, hi));
        }
        mx0 = redux_maxf(mx0);
        mx1 = redux_maxf(mx1);

        unsigned long long M0 = pk2(-mx0, -mx0), M1 = pk2(-mx1, -mx1);
        #pragma unroll
        for (int i = 0; i < 8; ++i) {
            float lo, hi;
            upk2(lo, hi, add2(e0[i], M0));
            e0[i] = pk2(ex2f_fast(lo), ex2f_fast(hi));
            upk2(lo, hi, add2(e1[i], M1));
            e1[i] = pk2(ex2f_fast(lo), ex2f_fast(hi));
        }

        // lane-partial sums (packed tree), then shfl-free REDUX warp sum
        float s0, s1;
        {
            unsigned long long t0 = add2(add2(add2(e0[0], e0[1]), add2(e0[2], e0[3])),
                                         add2(add2(e0[4], e0[5]), add2(e0[6], e0[7])));
            unsigned long long t1 = add2(add2(add2(e1[0], e1[1]), add2(e1[2], e1[3])),
                                         add2(add2(e1[4], e1[5]), add2(e1[6], e1[7])));
            float lo, hi;
            upk2(lo, hi, t0); s0 = lo + hi;
            upk2(lo, hi, t1); s1 = lo + hi;
        }
        s0 = redux_sum_pos(s0);
        s1 = redux_sum_pos(s1);

        unsigned long long v0, v1;
        {
            float i0 = rcpf_fast(s0), i1 = rcpf_fast(s1);
            v0 = pk2(i0, i0); v1 = pk2(i1, i1);
        }
        #pragma unroll
        for (int i = 0; i < 8; ++i) {
            A2[i] = fma2(e0[i], v0, A2[i]);
            A2[i] = fma2(e1[i], v1, A2[i]);
        }
    }

    #pragma unroll
    for (int i = 0; i < 8; ++i) {
        float lo, hi;
        upk2(lo, hi, A2[i]);
        atomicAdd(&Ash[lane + 64 * i], lo);
        atomicAdd(&Ash[lane + 64 * i + 32], hi);
    }
    __syncthreads();

    // top-12: JAX order (descending, ties -> lower index)
    if (warp == 0) {
        float av[16];
        #pragma unroll
        for (int j = 0; j < 16; ++j) av[j] = Ash[lane + 32 * j];
        #pragma unroll 1
        for (int t = 0; t < TOPK_N; ++t) {
            float bv = -CUDART_INF_F;
            int   bi = 0x7fffffff;
            #pragma unroll
            for (int j = 0; j < 16; ++j) {
                float v = av[j];
                if (v > bv) { bv = v; bi = lane + 32 * j; }
            }
            unsigned key = fkey(bv);
            unsigned win = __reduce_max_sync(0xffffffffu, key);
            unsigned cand = (key == win) ? (unsigned)bi : 0x7fffffffu;
            int idx = (int)__reduce_min_sync(0xffffffffu, cand);
            if (lane == 0) sel[t] = idx;
            #pragma unroll
            for (int j = 0; j < 16; ++j)
                if (idx == lane + 32 * j) av[j] = -CUDART_INF_F;
        }
    }
    __syncthreads();

    const float4* xb4 = (const float4*)(x + (size_t)b * NTOKS * DIN);
    float4* ob4 = (float4*)(out + (size_t)b * TOPK_N * DIN);
    for (int i = tid; i < TOPK_N * 32; i += NTHREADS) {
        int t  = i >> 5;
        int e4 = i & 31;
        ob4[i] = xb4[sel[t] * 32 + e4];
    }
}

extern "C" void kernel_launch(void* const* d_in, const int* in_sizes, int n_in,
                              void* d_out, int out_size)
{
    const float* x  = (const float*)d_in[0];
    const float* wk = (const float*)d_in[1];
    const float* wq = (const float*)d_in[2];
    float* out = (float*)d_out;
    (void)in_sizes; (void)n_in; (void)out_size;

    dim3 g1(8, NBATCH);
    proj_kernel<<<g1, NTHREADS>>>(x, wk, wq);
    attn_kernel<<<NBATCH, NTHREADS>>>(x, out);
}

// round 9
// speedup vs baseline: 1.1818x; 1.0193x over previous
#include <cuda_runtime.h>
#include <math_constants.h>
#include <cstdint>

#define NBATCH    512
#define NTOKS     512
#define DIN       128
#define TOPK_N    12
#define NTHREADS  256

// global scratch (contiguous per tensor for coalesced K2 loads)
__device__ float4 g_k[NBATCH * NTOKS];   // pre-scaled k
__device__ float4 g_q[NBATCH * NTOKS];

// ---------- PTX helpers ----------
__device__ __forceinline__ float ex2f_fast(float x) {
    float r; asm("ex2.approx.f32 %0, %1;" : "=f"(r) : "f"(x)); return r;
}
__device__ __forceinline__ float rcpf_fast(float x) {
    float r; asm("rcp.approx.f32 %0, %1;" : "=f"(r) : "f"(x)); return r;
}
__device__ __forceinline__ unsigned long long pk2(float lo, float hi) {
    unsigned long long r; asm("mov.b64 %0, {%1, %2};" : "=l"(r) : "f"(lo), "f"(hi)); return r;
}
__device__ __forceinline__ void upk2(float& lo, float& hi, unsigned long long v) {
    asm("mov.b64 {%0, %1}, %2;" : "=f"(lo), "=f"(hi) : "l"(v));
}
__device__ __forceinline__ unsigned long long fma2(unsigned long long a,
                                                   unsigned long long b,
                                                   unsigned long long c) {
    unsigned long long r;
    asm("fma.rn.f32x2 %0, %1, %2, %3;" : "=l"(r) : "l"(a), "l"(b), "l"(c));
    return r;
}
__device__ __forceinline__ unsigned long long add2(unsigned long long a,
                                                   unsigned long long b) {
    unsigned long long r;
    asm("add.rn.f32x2 %0, %1, %2;" : "=l"(r) : "l"(a), "l"(b));
    return r;
}
__device__ __forceinline__ void cp_async16(uint32_t saddr, const void* gaddr) {
    asm volatile("cp.async.cg.shared.global [%0], [%1], 16;" :: "r"(saddr), "l"(gaddr));
}
__device__ __forceinline__ unsigned fkey(float v) {
    int b = __float_as_int(v);
    return (unsigned)b ^ (unsigned)((b >> 31) | 0x80000000);
}

// ======================= K1: projection =======================
// grid (8, 512) = (chunk of 64 tokens, batch); 256 threads
__global__ __launch_bounds__(NTHREADS)
void proj_kernel(const float* __restrict__ x,
                 const float* __restrict__ wk,
                 const float* __restrict__ wq)
{
    __shared__ float xs[64 * 132];        // 528B token stride, conflict-free
    __shared__ float wks[512], wqs[512];
    __shared__ float4 sc4[128];

    const int tid = threadIdx.x;
    const int c = blockIdx.x;
    const int b = blockIdx.y;
    const float4* xg4 = (const float4*)(x + ((size_t)b * NTOKS + (size_t)c * 64) * DIN);

    for (int i = tid; i < 512; i += NTHREADS) { wks[i] = wk[i]; wqs[i] = wq[i]; }

    uint32_t xs_s = (uint32_t)__cvta_generic_to_shared(xs);
    #pragma unroll
    for (int k2 = 0; k2 < 8; ++k2) {
        int idx = tid + k2 * NTHREADS;          // 0..2047
        int t = idx >> 5, e4 = idx & 31;
        cp_async16(xs_s + (uint32_t)(t * 132 + e4 * 4) * 4u, xg4 + idx);
    }
    asm volatile("cp.async.commit_group;");
    asm volatile("cp.async.wait_group 0;");
    __syncthreads();

    const int token = tid & 63;
    const int dhalf = (tid >> 6) & 1;
    const int proj  = tid >> 7;
    const float4* wsel4 = (const float4*)(proj ? wqs : wks);
    const float4* xr = (const float4*)(xs + token * 132 + dhalf * 64);

    float a0 = 0.f, a1 = 0.f, a2 = 0.f, a3 = 0.f;
    #pragma unroll
    for (int i = 0; i < 16; ++i) {
        float4 xv = xr[i];
        int e4 = dhalf * 16 + i;
        float4 w0 = wsel4[e4 * 4 + 0];
        float4 w1 = wsel4[e4 * 4 + 1];
        float4 w2 = wsel4[e4 * 4 + 2];
        float4 w3 = wsel4[e4 * 4 + 3];
        a0 = fmaf(xv.x, w0.x, a0); a1 = fmaf(xv.x, w0.y, a1);
        a2 = fmaf(xv.x, w0.z, a2); a3 = fmaf(xv.x, w0.w, a3);
        a0 = fmaf(xv.y, w1.x, a0); a1 = fmaf(xv.y, w1.y, a1);
        a2 = fmaf(xv.y, w1.z, a2); a3 = fmaf(xv.y, w1.w, a3);
        a0 = fmaf(xv.z, w2.x, a0); a1 = fmaf(xv.z, w2.y, a1);
        a2 = fmaf(xv.z, w2.z, a2); a3 = fmaf(xv.z, w2.w, a3);
        a0 = fmaf(xv.w, w3.x, a0); a1 = fmaf(xv.w, w3.y, a1);
        a2 = fmaf(xv.w, w3.z, a2); a3 = fmaf(xv.w, w3.w, a3);
    }
    if (dhalf) sc4[proj * 64 + token] = make_float4(a0, a1, a2, a3);
    __syncthreads();
    if (!dhalf) {
        float4 p = sc4[proj * 64 + token];
        a0 += p.x; a1 += p.y; a2 += p.z; a3 += p.w;
        // (1/sqrt(128)) * log2(e) folded into k
        const float KSCALE = 0.0883883476483184405f * 1.4426950408889634074f;
        size_t o = (size_t)b * NTOKS + (size_t)c * 64 + token;
        if (proj == 0)
            g_k[o] = make_float4(a0 * KSCALE, a1 * KSCALE, a2 * KSCALE, a3 * KSCALE);
        else
            g_q[o] = make_float4(a0, a1, a2, a3);
    }
}

// ======================= K2: scores + softmax-sum + topk + gather ===========
// args = l - 100 (bias folded into dot accumulator). Per-row shift =
// max(rowmax_arg, 0), computed via an fmaxf tree seeded with 0.0f so every
// lane value is >= 0 and a raw s32 REDUX.MAX equals the float max. After the
// shift, args <= 0 ALWAYS: no overflow possible (round 6's inf->NaN and round
// 7's non-invariant clamp both closed), e <= 1, s in [1,512] -- numerics
// identical to the rounds that scored rel_err = 0. Dominant-term underflow
// would need rowmax < -26 sigma-ish: impossible.
__global__ __launch_bounds__(NTHREADS, 2)
void attn_kernel(const float* __restrict__ x, float* __restrict__ out)
{
    __shared__ float4 ks4[NTOKS];                 // pre-scaled k
    __shared__ unsigned long long qp[256 * 4];    // packed q pairs
    __shared__ float Ash[NTOKS];
    __shared__ int sel[16];

    const int tid  = threadIdx.x;
    const int lane = tid & 31;
    const int warp = tid >> 5;
    const int b    = blockIdx.x;
    const float4* kg = g_k + (size_t)b * NTOKS;
    const float4* qg = g_q + (size_t)b * NTOKS;

    // load k (coalesced)
    #pragma unroll
    for (int it = 0; it < 2; ++it) {
        int t = tid + it * NTHREADS;
        ks4[t] = kg[t];
    }
    // load + pack q: entry (i*32+ln) holds pairs for cols (ln+64i, ln+64i+32)
    {
        int i = tid >> 5, ln = tid & 31;
        int m = ln + 64 * i;
        float4 qa = qg[m];
        float4 qb = qg[m + 32];
        unsigned long long* dst = qp + (size_t)(i * 32 + ln) * 4;
        dst[0] = pk2(qa.x, qb.x);
        dst[1] = pk2(qa.y, qb.y);
        dst[2] = pk2(qa.z, qb.z);
        dst[3] = pk2(qa.w, qb.w);
    }
    for (int i = tid; i < NTOKS; i += NTHREADS) Ash[i] = 0.f;
    __syncthreads();

    // Q registers: lane owns cols lane+32j; pairs (lane+64i, lane+64i+32)
    unsigned long long Q[8][4];
    #pragma unroll
    for (int i = 0; i < 8; ++i) {
        const unsigned long long* src = qp + (size_t)(i * 32 + lane) * 4;
        Q[i][0] = src[0]; Q[i][1] = src[1]; Q[i][2] = src[2]; Q[i][3] = src[3];
    }

    const unsigned long long BIAS = pk2(-100.0f, -100.0f);

    unsigned long long A2[8];
    #pragma unroll
    for (int i = 0; i < 8; ++i) A2[i] = 0ull;

    #pragma unroll 1
    for (int rp = 0; rp < 32; ++rp) {
        int n = warp * 64 + rp * 2;
        float4 ka = ks4[n];
        float4 kb = ks4[n + 1];
        unsigned long long ka0 = pk2(ka.x, ka.x), ka1 = pk2(ka.y, ka.y);
        unsigned long long ka2 = pk2(ka.z, ka.z), ka3 = pk2(ka.w, ka.w);
        unsigned long long kb0 = pk2(kb.x, kb.x), kb1 = pk2(kb.y, kb.y);
        unsigned long long kb2 = pk2(kb.z, kb.z), kb3 = pk2(kb.w, kb.w);

        // dots with -100 bias folded into the accumulator init (args, packed)
        unsigned long long e0[8], e1[8];
        #pragma unroll
        for (int i = 0; i < 8; ++i) {
            unsigned long long a  = fma2(Q[i][0], ka0, BIAS);
            unsigned long long bb = fma2(Q[i][0], kb0, BIAS);
            a  = fma2(Q[i][1], ka1, a);  bb = fma2(Q[i][1], kb1, bb);
            a  = fma2(Q[i][2], ka2, a);  bb = fma2(Q[i][2], kb2, bb);
            a  = fma2(Q[i][3], ka3, a);  bb = fma2(Q[i][3], kb3, bb);
            e0[i] = a; e1[i] = bb;
        }

        // row shift = max(rowmax_arg, 0): fmaxf tree seeded with 0 ->
        // all lane values >= 0 -> raw s32 REDUX.MAX == float max (exact)
        float m0 = 0.0f, m1 = 0.0f;
        #pragma unroll
        for (int i = 0; i < 8; ++i) {
            float lo, hi;
            upk2(lo, hi, e0[i]); m0 = fmaxf(m0, fmaxf(lo, hi));
            upk2(lo, hi, e1[i]); m1 = fmaxf(m1, fmaxf(lo, hi));
        }
        m0 = __int_as_float(__reduce_max_sync(0xffffffffu, __float_as_int(m0)));
        m1 = __int_as_float(__reduce_max_sync(0xffffffffu, __float_as_int(m1)));

        // subtract shift (packed), exp2: args <= 0 -> e <= 1 always
        unsigned long long S0 = pk2(-m0, -m0), S1 = pk2(-m1, -m1);
        #pragma unroll
        for (int i = 0; i < 8; ++i) {
            float lo, hi;
            upk2(lo, hi, add2(e0[i], S0));
            e0[i] = pk2(ex2f_fast(lo), ex2f_fast(hi));
            upk2(lo, hi, add2(e1[i], S1));
            e1[i] = pk2(ex2f_fast(lo), ex2f_fast(hi));
        }

        // packed lane-sum trees, both rows' sums ride one f32x2 butterfly
        unsigned long long t0 = add2(add2(add2(e0[0], e0[1]), add2(e0[2], e0[3])),
                                     add2(add2(e0[4], e0[5]), add2(e0[6], e0[7])));
        unsigned long long t1 = add2(add2(add2(e1[0], e1[1]), add2(e1[2], e1[3])),
                                     add2(add2(e1[4], e1[5]), add2(e1[6], e1[7])));
        float lo, hi;
        upk2(lo, hi, t0); float s0 = lo + hi;
        upk2(lo, hi, t1); float s1 = lo + hi;
        unsigned long long s01 = pk2(s0, s1);
        #pragma unroll
        for (int off = 16; off > 0; off >>= 1)
            s01 = add2(s01, __shfl_xor_sync(0xffffffffu, s01, off));
        upk2(s0, s1, s01);

        unsigned long long v0, v1;
        {
            float i0 = rcpf_fast(s0), i1 = rcpf_fast(s1);
            v0 = pk2(i0, i0); v1 = pk2(i1, i1);
        }
        #pragma unroll
        for (int i = 0; i < 8; ++i) {
            A2[i] = fma2(e0[i], v0, A2[i]);
            A2[i] = fma2(e1[i], v1, A2[i]);
        }
    }

    #pragma unroll
    for (int i = 0; i < 8; ++i) {
        float lo, hi;
        upk2(lo, hi, A2[i]);
        atomicAdd(&Ash[lane + 64 * i], lo);
        atomicAdd(&Ash[lane + 64 * i + 32], hi);
    }
    __syncthreads();

    // top-12: JAX order (descending, ties -> lower index)
    if (warp == 0) {
        float av[16];
        #pragma unroll
        for (int j = 0; j < 16; ++j) av[j] = Ash[lane + 32 * j];
        #pragma unroll 1
        for (int t = 0; t < TOPK_N; ++t) {
            float bv = -CUDART_INF_F;
            int   bi = 0x7fffffff;
            #pragma unroll
            for (int j = 0; j < 16; ++j) {
                float v = av[j];
                if (v > bv) { bv = v; bi = lane + 32 * j; }
            }
            unsigned key = fkey(bv);
            unsigned win = __reduce_max_sync(0xffffffffu, key);
            unsigned cand = (key == win) ? (unsigned)bi : 0x7fffffffu;
            int idx = (int)__reduce_min_sync(0xffffffffu, cand);
            if (lane == 0) sel[t] = idx;
            #pragma unroll
            for (int j = 0; j < 16; ++j)
                if (idx == lane + 32 * j) av[j] = -CUDART_INF_F;
        }
    }
    __syncthreads();

    const float4* xb4 = (const float4*)(x + (size_t)b * NTOKS * DIN);
    float4* ob4 = (float4*)(out + (size_t)b * TOPK_N * DIN);
    for (int i = tid; i < TOPK_N * 32; i += NTHREADS) {
        int t  = i >> 5;
        int e4 = i & 31;
        ob4[i] = xb4[sel[t] * 32 + e4];
    }
}

extern "C" void kernel_launch(void* const* d_in, const int* in_sizes, int n_in,
                              void* d_out, int out_size)
{
    const float* x  = (const float*)d_in[0];
    const float* wk = (const float*)d_in[1];
    const float* wq = (const float*)d_in[2];
    float* out = (float*)d_out;
    (void)in_sizes; (void)n_in; (void)out_size;

    dim3 g1(8, NBATCH);
    proj_kernel<<<g1, NTHREADS>>>(x, wk, wq);
    attn_kernel<<<NBATCH, NTHREADS>>>(x, out);
}

// round 10
// speedup vs baseline: 1.2192x; 1.0317x over previous
#include <cuda_runtime.h>
#include <math_constants.h>
#include <cstdint>

#define NBATCH    512
#define NTOKS     512
#define DIN       128
#define TOPK_N    12
#define NTHREADS  256

// global scratch (contiguous per tensor for coalesced K2 loads)
__device__ float4 g_k[NBATCH * NTOKS];   // pre-scaled k
__device__ float4 g_q[NBATCH * NTOKS];

// ---------- PTX helpers ----------
__device__ __forceinline__ float ex2f_fast(float x) {
    float r; asm("ex2.approx.f32 %0, %1;" : "=f"(r) : "f"(x)); return r;
}
__device__ __forceinline__ float rcpf_fast(float x) {
    float r; asm("rcp.approx.f32 %0, %1;" : "=f"(r) : "f"(x)); return r;
}
__device__ __forceinline__ unsigned long long pk2(float lo, float hi) {
    unsigned long long r; asm("mov.b64 %0, {%1, %2};" : "=l"(r) : "f"(lo), "f"(hi)); return r;
}
__device__ __forceinline__ void upk2(float& lo, float& hi, unsigned long long v) {
    asm("mov.b64 {%0, %1}, %2;" : "=f"(lo), "=f"(hi) : "l"(v));
}
__device__ __forceinline__ unsigned long long fma2(unsigned long long a,
                                                   unsigned long long b,
                                                   unsigned long long c) {
    unsigned long long r;
    asm("fma.rn.f32x2 %0, %1, %2, %3;" : "=l"(r) : "l"(a), "l"(b), "l"(c));
    return r;
}
__device__ __forceinline__ unsigned long long add2(unsigned long long a,
                                                   unsigned long long b) {
    unsigned long long r;
    asm("add.rn.f32x2 %0, %1, %2;" : "=l"(r) : "l"(a), "l"(b));
    return r;
}
__device__ __forceinline__ void cp_async16(uint32_t saddr, const void* gaddr) {
    asm volatile("cp.async.cg.shared.global [%0], [%1], 16;" :: "r"(saddr), "l"(gaddr));
}
__device__ __forceinline__ unsigned fkey(float v) {
    int b = __float_as_int(v);
    return (unsigned)b ^ (unsigned)((b >> 31) | 0x80000000);
}

// ======================= K1: projection (unchanged, proven) =================
// grid (8, 512) = (chunk of 64 tokens, batch); 256 threads
__global__ __launch_bounds__(NTHREADS)
void proj_kernel(const float* __restrict__ x,
                 const float* __restrict__ wk,
                 const float* __restrict__ wq)
{
    __shared__ float xs[64 * 132];        // 528B token stride, conflict-free
    __shared__ float wks[512], wqs[512];
    __shared__ float4 sc4[128];

    const int tid = threadIdx.x;
    const int c = blockIdx.x;
    const int b = blockIdx.y;
    const float4* xg4 = (const float4*)(x + ((size_t)b * NTOKS + (size_t)c * 64) * DIN);

    for (int i = tid; i < 512; i += NTHREADS) { wks[i] = wk[i]; wqs[i] = wq[i]; }

    uint32_t xs_s = (uint32_t)__cvta_generic_to_shared(xs);
    #pragma unroll
    for (int k2 = 0; k2 < 8; ++k2) {
        int idx = tid + k2 * NTHREADS;          // 0..2047
        int t = idx >> 5, e4 = idx & 31;
        cp_async16(xs_s + (uint32_t)(t * 132 + e4 * 4) * 4u, xg4 + idx);
    }
    asm volatile("cp.async.commit_group;");
    asm volatile("cp.async.wait_group 0;");
    __syncthreads();

    const int token = tid & 63;
    const int dhalf = (tid >> 6) & 1;
    const int proj  = tid >> 7;
    const float4* wsel4 = (const float4*)(proj ? wqs : wks);
    const float4* xr = (const float4*)(xs + token * 132 + dhalf * 64);

    float a0 = 0.f, a1 = 0.f, a2 = 0.f, a3 = 0.f;
    #pragma unroll
    for (int i = 0; i < 16; ++i) {
        float4 xv = xr[i];
        int e4 = dhalf * 16 + i;
        float4 w0 = wsel4[e4 * 4 + 0];
        float4 w1 = wsel4[e4 * 4 + 1];
        float4 w2 = wsel4[e4 * 4 + 2];
        float4 w3 = wsel4[e4 * 4 + 3];
        a0 = fmaf(xv.x, w0.x, a0); a1 = fmaf(xv.x, w0.y, a1);
        a2 = fmaf(xv.x, w0.z, a2); a3 = fmaf(xv.x, w0.w, a3);
        a0 = fmaf(xv.y, w1.x, a0); a1 = fmaf(xv.y, w1.y, a1);
        a2 = fmaf(xv.y, w1.z, a2); a3 = fmaf(xv.y, w1.w, a3);
        a0 = fmaf(xv.z, w2.x, a0); a1 = fmaf(xv.z, w2.y, a1);
        a2 = fmaf(xv.z, w2.z, a2); a3 = fmaf(xv.z, w2.w, a3);
        a0 = fmaf(xv.w, w3.x, a0); a1 = fmaf(xv.w, w3.y, a1);
        a2 = fmaf(xv.w, w3.z, a2); a3 = fmaf(xv.w, w3.w, a3);
    }
    if (dhalf) sc4[proj * 64 + token] = make_float4(a0, a1, a2, a3);
    __syncthreads();
    if (!dhalf) {
        float4 p = sc4[proj * 64 + token];
        a0 += p.x; a1 += p.y; a2 += p.z; a3 += p.w;
        // (1/sqrt(128)) * log2(e) folded into k
        const float KSCALE = 0.0883883476483184405f * 1.4426950408889634074f;
        size_t o = (size_t)b * NTOKS + (size_t)c * 64 + token;
        if (proj == 0)
            g_k[o] = make_float4(a0 * KSCALE, a1 * KSCALE, a2 * KSCALE, a3 * KSCALE);
        else
            g_q[o] = make_float4(a0, a1, a2, a3);
    }
}

// ======================= K2: scores + softmax-sum + topk + gather ===========
// Same math as the round-9 rel_err=0 kernel. Change: Q lives in SMEM (not 64
// registers) in a transposed conflict-free layout and is re-loaded per
// row-pair (16 LDS.128/pair, LSU was idle). regs 128 -> ~64 so 4 CTAs/SM:
// 8 warps/SMSP hide the reduction chain, and 512 CTAs <= 148*4 = one wave.
__global__ __launch_bounds__(NTHREADS, 4)
void attn_kernel(const float* __restrict__ x, float* __restrict__ out)
{
    __shared__ float4 ks4[NTOKS];                 // pre-scaled k (8 KB)
    // qp2[pair p][lane]: .x = Q slot 2p, .y = slot 2p+1 (p = 0..15). Lane
    // stride 16B -> 4-phase conflict-free LDS.128 / STS.128. (8 KB)
    __shared__ ulonglong2 qp2[16 * 32];
    __shared__ float Ash[NTOKS];
    __shared__ int sel[16];

    const int tid  = threadIdx.x;
    const int lane = tid & 31;
    const int warp = tid >> 5;
    const int b    = blockIdx.x;
    const float4* kg = g_k + (size_t)b * NTOKS;
    const float4* qg = g_q + (size_t)b * NTOKS;

    // load k (coalesced)
    #pragma unroll
    for (int it = 0; it < 2; ++it) {
        int t = tid + it * NTHREADS;
        ks4[t] = kg[t];
    }
    // load + pack q. Thread (i = tid>>5, ln): lane ln owns cols ln+32j;
    // slot 4i+c packs (col ln+64i, col ln+64i+32) component c.
    {
        int i = tid >> 5, ln = tid & 31;
        int m = ln + 64 * i;
        float4 qa = qg[m];
        float4 qb = qg[m + 32];
        ulonglong2 lo, hi;
        lo.x = pk2(qa.x, qb.x);  lo.y = pk2(qa.y, qb.y);   // slots 4i, 4i+1
        hi.x = pk2(qa.z, qb.z);  hi.y = pk2(qa.w, qb.w);   // slots 4i+2, 4i+3
        qp2[(2 * i) * 32 + ln]     = lo;
        qp2[(2 * i + 1) * 32 + ln] = hi;
    }
    for (int i = tid; i < NTOKS; i += NTHREADS) Ash[i] = 0.f;
    __syncthreads();

    const unsigned long long BIAS = pk2(-100.0f, -100.0f);

    unsigned long long A2[8];
    #pragma unroll
    for (int i = 0; i < 8; ++i) A2[i] = 0ull;

    #pragma unroll 1
    for (int rp = 0; rp < 32; ++rp) {
        int n = warp * 64 + rp * 2;
        float4 ka = ks4[n];
        float4 kb = ks4[n + 1];
        unsigned long long ka0 = pk2(ka.x, ka.x), ka1 = pk2(ka.y, ka.y);
        unsigned long long ka2 = pk2(ka.z, ka.z), ka3 = pk2(ka.w, ka.w);
        unsigned long long kb0 = pk2(kb.x, kb.x), kb1 = pk2(kb.y, kb.y);
        unsigned long long kb2 = pk2(kb.z, kb.z), kb3 = pk2(kb.w, kb.w);

        // dots with -100 bias folded into the accumulator init; Q from smem
        unsigned long long e0[8], e1[8];
        #pragma unroll
        for (int i = 0; i < 8; ++i) {
            ulonglong2 qA = qp2[(2 * i) * 32 + lane];       // slots 4i, 4i+1
            ulonglong2 qB = qp2[(2 * i + 1) * 32 + lane];   // slots 4i+2, 4i+3
            unsigned long long a  = fma2(qA.x, ka0, BIAS);
            unsigned long long bb = fma2(qA.x, kb0, BIAS);
            a  = fma2(qA.y, ka1, a);  bb = fma2(qA.y, kb1, bb);
            a  = fma2(qB.x, ka2, a);  bb = fma2(qB.x, kb2, bb);
            a  = fma2(qB.y, ka3, a);  bb = fma2(qB.y, kb3, bb);
            e0[i] = a; e1[i] = bb;
        }

        // row shift = max(rowmax_arg, 0): fmaxf tree seeded with 0 ->
        // all lane values >= 0 -> raw s32 REDUX.MAX == float max (exact)
        float m0 = 0.0f, m1 = 0.0f;
        #pragma unroll
        for (int i = 0; i < 8; ++i) {
            float lo, hi;
            upk2(lo, hi, e0[i]); m0 = fmaxf(m0, fmaxf(lo, hi));
            upk2(lo, hi, e1[i]); m1 = fmaxf(m1, fmaxf(lo, hi));
        }
        m0 = __int_as_float(__reduce_max_sync(0xffffffffu, __float_as_int(m0)));
        m1 = __int_as_float(__reduce_max_sync(0xffffffffu, __float_as_int(m1)));

        // subtract shift (packed), exp2: args <= 0 -> e <= 1 always
        unsigned long long S0 = pk2(-m0, -m0), S1 = pk2(-m1, -m1);
        #pragma unroll
        for (int i = 0; i < 8; ++i) {
            float lo, hi;
            upk2(lo, hi, add2(e0[i], S0));
            e0[i] = pk2(ex2f_fast(lo), ex2f_fast(hi));
            upk2(lo, hi, add2(e1[i], S1));
            e1[i] = pk2(ex2f_fast(lo), ex2f_fast(hi));
        }

        // packed lane-sum trees, both rows' sums ride one f32x2 butterfly
        unsigned long long t0 = add2(add2(add2(e0[0], e0[1]), add2(e0[2], e0[3])),
                                     add2(add2(e0[4], e0[5]), add2(e0[6], e0[7])));
        unsigned long long t1 = add2(add2(add2(e1[0], e1[1]), add2(e1[2], e1[3])),
                                     add2(add2(e1[4], e1[5]), add2(e1[6], e1[7])));
        float lo, hi;
        upk2(lo, hi, t0); float s0 = lo + hi;
        upk2(lo, hi, t1); float s1 = lo + hi;
        unsigned long long s01 = pk2(s0, s1);
        #pragma unroll
        for (int off = 16; off > 0; off >>= 1)
            s01 = add2(s01, __shfl_xor_sync(0xffffffffu, s01, off));
        upk2(s0, s1, s01);

        unsigned long long v0, v1;
        {
            float i0 = rcpf_fast(s0), i1 = rcpf_fast(s1);
            v0 = pk2(i0, i0); v1 = pk2(i1, i1);
        }
        #pragma unroll
        for (int i = 0; i < 8; ++i) {
            A2[i] = fma2(e0[i], v0, A2[i]);
            A2[i] = fma2(e1[i], v1, A2[i]);
        }
    }

    #pragma unroll
    for (int i = 0; i < 8; ++i) {
        float lo, hi;
        upk2(lo, hi, A2[i]);
        atomicAdd(&Ash[lane + 64 * i], lo);
        atomicAdd(&Ash[lane + 64 * i + 32], hi);
    }
    __syncthreads();

    // top-12: JAX order (descending, ties -> lower index)
    if (warp == 0) {
        float av[16];
        #pragma unroll
        for (int j = 0; j < 16; ++j) av[j] = Ash[lane + 32 * j];
        #pragma unroll 1
        for (int t = 0; t < TOPK_N; ++t) {
            float bv = -CUDART_INF_F;
            int   bi = 0x7fffffff;
            #pragma unroll
            for (int j = 0; j < 16; ++j) {
                float v = av[j];
                if (v > bv) { bv = v; bi = lane + 32 * j; }
            }
            unsigned key = fkey(bv);
            unsigned win = __reduce_max_sync(0xffffffffu, key);
            unsigned cand = (key == win) ? (unsigned)bi : 0x7fffffffu;
            int idx = (int)__reduce_min_sync(0xffffffffu, cand);
            if (lane == 0) sel[t] = idx;
            #pragma unroll
            for (int j = 0; j < 16; ++j)
                if (idx == lane + 32 * j) av[j] = -CUDART_INF_F;
        }
    }
    __syncthreads();

    const float4* xb4 = (const float4*)(x + (size_t)b * NTOKS * DIN);
    float4* ob4 = (float4*)(out + (size_t)b * TOPK_N * DIN);
    for (int i = tid; i < TOPK_N * 32; i += NTHREADS) {
        int t  = i >> 5;
        int e4 = i & 31;
        ob4[i] = xb4[sel[t] * 32 + e4];
    }
}

extern "C" void kernel_launch(void* const* d_in, const int* in_sizes, int n_in,
                              void* d_out, int out_size)
{
    const float* x  = (const float*)d_in[0];
    const float* wk = (const float*)d_in[1];
    const float* wq = (const float*)d_in[2];
    float* out = (float*)d_out;
    (void)in_sizes; (void)n_in; (void)out_size;

    dim3 g1(8, NBATCH);
    proj_kernel<<<g1, NTHREADS>>>(x, wk, wq);
    attn_kernel<<<NBATCH, NTHREADS>>>(x, out);
}